// round 4
// baseline (speedup 1.0000x reference)
#include <cuda_runtime.h>
#include <math.h>

// Problem constants
#define BATCH 4
#define CCH   512
#define HWN   4096          // H*W
#define NGRP  32
#define CPG   16            // channels per group
#define CHW   (CCH*HWN)     // 2097152 per-batch elements

// GEMM tiling
#define BM 128
#define BN 128
#define BK 16
#define PAD 4
#define LDS_ (BM + PAD)     // 132 floats per shared row

// ---------------------------------------------------------------------------
// Scratch (static device allocations; no cudaMalloc allowed)
// ---------------------------------------------------------------------------
__device__ float g_h[BATCH * CHW];                 // groupnormed, flat (B,HW,C)==(B,C,HW)
__device__ float g_q[BATCH * CHW];
__device__ float g_k[BATCH * CHW];
__device__ float g_v[BATCH * CHW];
__device__ float g_o[BATCH * CHW];                 // attention output, (C,HW) per batch
__device__ float g_attn[(size_t)BATCH * HWN * HWN];// 268 MB logits/probs
__device__ float g_mu[BATCH * NGRP];
__device__ float g_rs[BATCH * NGRP];

// ---------------------------------------------------------------------------
// GroupNorm
// ---------------------------------------------------------------------------
__global__ void gn_stats(const float* __restrict__ x) {
    int bg = blockIdx.x;                                   // 0..127  (b*32+g)
    const float* p = x + (size_t)bg * (CPG * HWN);         // contiguous 65536 floats
    float s = 0.f, ss = 0.f;
    for (int i = threadIdx.x * 4; i < CPG * HWN; i += blockDim.x * 4) {
        float4 v = *(const float4*)(p + i);
        s  += v.x + v.y + v.z + v.w;
        ss += v.x * v.x + v.y * v.y + v.z * v.z + v.w * v.w;
    }
    __shared__ float sh[64];
    #pragma unroll
    for (int o = 16; o; o >>= 1) {
        s  += __shfl_down_sync(0xffffffffu, s, o);
        ss += __shfl_down_sync(0xffffffffu, ss, o);
    }
    int w = threadIdx.x >> 5, l = threadIdx.x & 31;
    if (l == 0) { sh[w] = s; sh[32 + w] = ss; }
    __syncthreads();
    if (w == 0) {
        s  = (l < (int)(blockDim.x >> 5)) ? sh[l] : 0.f;
        ss = (l < (int)(blockDim.x >> 5)) ? sh[32 + l] : 0.f;
        #pragma unroll
        for (int o = 16; o; o >>= 1) {
            s  += __shfl_down_sync(0xffffffffu, s, o);
            ss += __shfl_down_sync(0xffffffffu, ss, o);
        }
        if (l == 0) {
            float mu = s * (1.f / 65536.f);
            float var = ss * (1.f / 65536.f) - mu * mu;
            g_mu[bg] = mu;
            g_rs[bg] = rsqrtf(var + 1e-5f);
        }
    }
}

__global__ void gn_apply(const float* __restrict__ x,
                         const float* __restrict__ gw,
                         const float* __restrict__ gb) {
    size_t i = ((size_t)blockIdx.x * blockDim.x + threadIdx.x) * 4;
    if (i >= (size_t)BATCH * CHW) return;
    float4 v = *(const float4*)(x + i);
    int c  = (int)((i >> 12) & 511);     // (i/4096) % 512
    int bg = (int)(i >> 16);             // i/65536 == b*32+g
    float rs = g_rs[bg];
    float sc = rs * gw[c];
    float sb = gb[c] - g_mu[bg] * sc;
    v.x = v.x * sc + sb; v.y = v.y * sc + sb;
    v.z = v.z * sc + sb; v.w = v.w * sc + sb;
    *(float4*)(g_h + i) = v;
}

// ---------------------------------------------------------------------------
// GEMM 1: QKV.  C[m,n] = sum_k A[m,k]*W[n,k] + bias[n]
// A = g_h (16384 x 512 row-major), W row-major (512 x 512). blockIdx.z picks q/k/v.
// ---------------------------------------------------------------------------
__global__ __launch_bounds__(256) void k_qkv(
    const float* __restrict__ wq, const float* __restrict__ wk, const float* __restrict__ wv,
    const float* __restrict__ bq, const float* __restrict__ bk, const float* __restrict__ bv) {
    const float *W, *bias; float* O;
    if      (blockIdx.z == 0) { W = wq; bias = bq; O = g_q; }
    else if (blockIdx.z == 1) { W = wk; bias = bk; O = g_k; }
    else                      { W = wv; bias = bv; O = g_v; }
    const int K = 512, N = 512;
    int bm = blockIdx.y * BM, bn = blockIdx.x * BN;
    __shared__ float As[BK][LDS_], Bs[BK][LDS_];
    int tid = threadIdx.x;
    int lr = tid >> 2, lc = (tid & 3) * 4;
    int ty = tid >> 4, tx = tid & 15;
    float acc[8][8] = {};
    for (int k0 = 0; k0 < K; k0 += BK) {
        #pragma unroll
        for (int p = 0; p < 2; p++) {
            int r = lr + p * 64;
            float4 a = *(const float4*)(g_h + (size_t)(bm + r) * K + k0 + lc);
            As[lc][r] = a.x; As[lc+1][r] = a.y; As[lc+2][r] = a.z; As[lc+3][r] = a.w;
            float4 b = *(const float4*)(W + (size_t)(bn + r) * K + k0 + lc);
            Bs[lc][r] = b.x; Bs[lc+1][r] = b.y; Bs[lc+2][r] = b.z; Bs[lc+3][r] = b.w;
        }
        __syncthreads();
        #pragma unroll
        for (int k = 0; k < BK; k++) {
            float ar[8], br[8];
            *(float4*)ar       = *(float4*)&As[k][ty * 4];
            *(float4*)(ar + 4) = *(float4*)&As[k][64 + ty * 4];
            *(float4*)br       = *(float4*)&Bs[k][tx * 4];
            *(float4*)(br + 4) = *(float4*)&Bs[k][64 + tx * 4];
            #pragma unroll
            for (int i = 0; i < 8; i++)
                #pragma unroll
                for (int j = 0; j < 8; j++)
                    acc[i][j] += ar[i] * br[j];
        }
        __syncthreads();
    }
    float bb[8];
    #pragma unroll
    for (int j = 0; j < 4; j++) { bb[j] = bias[bn + tx*4 + j]; bb[j+4] = bias[bn + 64 + tx*4 + j]; }
    #pragma unroll
    for (int i = 0; i < 8; i++) {
        int m = bm + ((i < 4) ? (ty*4 + i) : (64 + ty*4 + i - 4));
        float4 v0 = { acc[i][0]+bb[0], acc[i][1]+bb[1], acc[i][2]+bb[2], acc[i][3]+bb[3] };
        float4 v1 = { acc[i][4]+bb[4], acc[i][5]+bb[5], acc[i][6]+bb[6], acc[i][7]+bb[7] };
        *(float4*)(O + (size_t)m * N + bn + tx*4)      = v0;
        *(float4*)(O + (size_t)m * N + bn + 64 + tx*4) = v1;
    }
}

// ---------------------------------------------------------------------------
// GEMM 2: attn logits.  C[n,m] = sum_c Q[c,n]*Kx[c,m]   (per batch, z=batch)
// Q,K viewed (512 x 4096) row-major, ld=4096. C = g_attn (4096x4096).
// ---------------------------------------------------------------------------
__global__ __launch_bounds__(256) void k_qtk() {
    int b = blockIdx.z;
    const float* A = g_q + (size_t)b * CHW;
    const float* Bp = g_k + (size_t)b * CHW;
    float* Cm = g_attn + (size_t)b * HWN * HWN;
    const int K = 512;
    int bm = blockIdx.y * BM, bn = blockIdx.x * BN;
    __shared__ float As[BK][LDS_], Bs[BK][LDS_];
    int tid = threadIdx.x;
    int kr = tid >> 5, mc = (tid & 31) * 4;
    int ty = tid >> 4, tx = tid & 15;
    float acc[8][8] = {};
    for (int k0 = 0; k0 < K; k0 += BK) {
        #pragma unroll
        for (int p = 0; p < 2; p++) {
            int r = kr + p * 8;
            *(float4*)&As[r][mc] = *(const float4*)(A  + (size_t)(k0 + r) * HWN + bm + mc);
            *(float4*)&Bs[r][mc] = *(const float4*)(Bp + (size_t)(k0 + r) * HWN + bn + mc);
        }
        __syncthreads();
        #pragma unroll
        for (int k = 0; k < BK; k++) {
            float ar[8], br[8];
            *(float4*)ar       = *(float4*)&As[k][ty * 4];
            *(float4*)(ar + 4) = *(float4*)&As[k][64 + ty * 4];
            *(float4*)br       = *(float4*)&Bs[k][tx * 4];
            *(float4*)(br + 4) = *(float4*)&Bs[k][64 + tx * 4];
            #pragma unroll
            for (int i = 0; i < 8; i++)
                #pragma unroll
                for (int j = 0; j < 8; j++)
                    acc[i][j] += ar[i] * br[j];
        }
        __syncthreads();
    }
    #pragma unroll
    for (int i = 0; i < 8; i++) {
        int m = bm + ((i < 4) ? (ty*4 + i) : (64 + ty*4 + i - 4));
        float4 v0 = { acc[i][0], acc[i][1], acc[i][2], acc[i][3] };
        float4 v1 = { acc[i][4], acc[i][5], acc[i][6], acc[i][7] };
        *(float4*)(Cm + (size_t)m * HWN + bn + tx*4)      = v0;
        *(float4*)(Cm + (size_t)m * HWN + bn + 64 + tx*4) = v1;
    }
}

// ---------------------------------------------------------------------------
// Softmax over last dim (4096) of g_attn, in place. One block per row.
// ---------------------------------------------------------------------------
__global__ __launch_bounds__(256) void k_softmax() {
    __shared__ float buf[HWN];
    __shared__ float red[33];
    size_t row = blockIdx.x;
    float* p = g_attn + row * HWN;
    int tid = threadIdx.x;
    float mx = -1e30f;
    for (int i = tid * 4; i < HWN; i += 1024) {
        float4 v = *(const float4*)(p + i);
        *(float4*)(buf + i) = v;
        mx = fmaxf(mx, fmaxf(fmaxf(v.x, v.y), fmaxf(v.z, v.w)));
    }
    #pragma unroll
    for (int o = 16; o; o >>= 1) mx = fmaxf(mx, __shfl_xor_sync(0xffffffffu, mx, o));
    if ((tid & 31) == 0) red[tid >> 5] = mx;
    __syncthreads();
    if (tid < 32) {
        float m2 = (tid < 8) ? red[tid] : -1e30f;
        #pragma unroll
        for (int o = 4; o; o >>= 1) m2 = fmaxf(m2, __shfl_xor_sync(0xffffffffu, m2, o));
        if (tid == 0) red[32] = m2;
    }
    __syncthreads();
    mx = red[32];
    float s = 0.f;
    for (int i = tid * 4; i < HWN; i += 1024) {
        float4 v = *(float4*)(buf + i);
        v.x = __expf(v.x - mx); v.y = __expf(v.y - mx);
        v.z = __expf(v.z - mx); v.w = __expf(v.w - mx);
        *(float4*)(buf + i) = v;
        s += v.x + v.y + v.z + v.w;
    }
    #pragma unroll
    for (int o = 16; o; o >>= 1) s += __shfl_xor_sync(0xffffffffu, s, o);
    if ((tid & 31) == 0) red[tid >> 5] = s;
    __syncthreads();
    if (tid < 32) {
        float s2 = (tid < 8) ? red[tid] : 0.f;
        #pragma unroll
        for (int o = 4; o; o >>= 1) s2 += __shfl_xor_sync(0xffffffffu, s2, o);
        if (tid == 0) red[32] = s2;
    }
    __syncthreads();
    float inv = 1.f / red[32];
    for (int i = tid * 4; i < HWN; i += 1024) {
        float4 v = *(float4*)(buf + i);
        v.x *= inv; v.y *= inv; v.z *= inv; v.w *= inv;
        *(float4*)(p + i) = v;
    }
}

// ---------------------------------------------------------------------------
// GEMM 3: O[c,n] = sum_m V[c,m]*P[n,m]   (per batch).  M=512, N=4096, K=4096.
// ---------------------------------------------------------------------------
__global__ __launch_bounds__(256) void k_vpt() {
    int b = blockIdx.z;
    const float* A = g_v + (size_t)b * CHW;                // 512 x 4096 row-major
    const float* Bp = g_attn + (size_t)b * HWN * HWN;      // 4096 x 4096 row-major
    float* Cm = g_o + (size_t)b * CHW;
    const int K = HWN;
    int bm = blockIdx.y * BM, bn = blockIdx.x * BN;
    __shared__ float As[BK][LDS_], Bs[BK][LDS_];
    int tid = threadIdx.x;
    int lr = tid >> 2, lc = (tid & 3) * 4;
    int ty = tid >> 4, tx = tid & 15;
    float acc[8][8] = {};
    for (int k0 = 0; k0 < K; k0 += BK) {
        #pragma unroll
        for (int p = 0; p < 2; p++) {
            int r = lr + p * 64;
            float4 a = *(const float4*)(A + (size_t)(bm + r) * K + k0 + lc);
            As[lc][r] = a.x; As[lc+1][r] = a.y; As[lc+2][r] = a.z; As[lc+3][r] = a.w;
            float4 bb = *(const float4*)(Bp + (size_t)(bn + r) * K + k0 + lc);
            Bs[lc][r] = bb.x; Bs[lc+1][r] = bb.y; Bs[lc+2][r] = bb.z; Bs[lc+3][r] = bb.w;
        }
        __syncthreads();
        #pragma unroll
        for (int k = 0; k < BK; k++) {
            float ar[8], br[8];
            *(float4*)ar       = *(float4*)&As[k][ty * 4];
            *(float4*)(ar + 4) = *(float4*)&As[k][64 + ty * 4];
            *(float4*)br       = *(float4*)&Bs[k][tx * 4];
            *(float4*)(br + 4) = *(float4*)&Bs[k][64 + tx * 4];
            #pragma unroll
            for (int i = 0; i < 8; i++)
                #pragma unroll
                for (int j = 0; j < 8; j++)
                    acc[i][j] += ar[i] * br[j];
        }
        __syncthreads();
    }
    #pragma unroll
    for (int i = 0; i < 8; i++) {
        int m = bm + ((i < 4) ? (ty*4 + i) : (64 + ty*4 + i - 4));
        float4 v0 = { acc[i][0], acc[i][1], acc[i][2], acc[i][3] };
        float4 v1 = { acc[i][4], acc[i][5], acc[i][6], acc[i][7] };
        *(float4*)(Cm + (size_t)m * HWN + bn + tx*4)      = v0;
        *(float4*)(Cm + (size_t)m * HWN + bn + 64 + tx*4) = v1;
    }
}

// ---------------------------------------------------------------------------
// GEMM 4 (final): Y[n,co] = sum_ci O[ci,n]*Wo[co,ci] + bo[co] + x_flat[n*512+co]
// per batch; output written to d_out at b*CHW + n*512 + co.
// ---------------------------------------------------------------------------
__global__ __launch_bounds__(256) void k_final(
    const float* __restrict__ wo, const float* __restrict__ bo,
    const float* __restrict__ x, float* __restrict__ out) {
    int b = blockIdx.z;
    const float* A = g_o + (size_t)b * CHW;   // K=512 rows x M=4096 cols, ld 4096
    const int K = 512, N = 512;
    int bm = blockIdx.y * BM, bn = blockIdx.x * BN;
    __shared__ float As[BK][LDS_], Bs[BK][LDS_];
    int tid = threadIdx.x;
    int kr = tid >> 5, mc = (tid & 31) * 4;   // A fetch (TN style)
    int lr = tid >> 2, lc = (tid & 3) * 4;    // W fetch (NT style)
    int ty = tid >> 4, tx = tid & 15;
    float acc[8][8] = {};
    for (int k0 = 0; k0 < K; k0 += BK) {
        #pragma unroll
        for (int p = 0; p < 2; p++) {
            int r = kr + p * 8;
            *(float4*)&As[r][mc] = *(const float4*)(A + (size_t)(k0 + r) * HWN + bm + mc);
            int r2 = lr + p * 64;
            float4 w = *(const float4*)(wo + (size_t)(bn + r2) * K + k0 + lc);
            Bs[lc][r2] = w.x; Bs[lc+1][r2] = w.y; Bs[lc+2][r2] = w.z; Bs[lc+3][r2] = w.w;
        }
        __syncthreads();
        #pragma unroll
        for (int k = 0; k < BK; k++) {
            float ar[8], br[8];
            *(float4*)ar       = *(float4*)&As[k][ty * 4];
            *(float4*)(ar + 4) = *(float4*)&As[k][64 + ty * 4];
            *(float4*)br       = *(float4*)&Bs[k][tx * 4];
            *(float4*)(br + 4) = *(float4*)&Bs[k][64 + tx * 4];
            #pragma unroll
            for (int i = 0; i < 8; i++)
                #pragma unroll
                for (int j = 0; j < 8; j++)
                    acc[i][j] += ar[i] * br[j];
        }
        __syncthreads();
    }
    float bb[8];
    #pragma unroll
    for (int j = 0; j < 4; j++) { bb[j] = bo[bn + tx*4 + j]; bb[j+4] = bo[bn + 64 + tx*4 + j]; }
    const float* xb = x + (size_t)b * CHW;
    float* ob = out + (size_t)b * CHW;
    #pragma unroll
    for (int i = 0; i < 8; i++) {
        int m = bm + ((i < 4) ? (ty*4 + i) : (64 + ty*4 + i - 4));
        size_t base = (size_t)m * N;
        float4 x0 = *(const float4*)(xb + base + bn + tx*4);
        float4 x1 = *(const float4*)(xb + base + bn + 64 + tx*4);
        float4 v0 = { acc[i][0]+bb[0]+x0.x, acc[i][1]+bb[1]+x0.y,
                      acc[i][2]+bb[2]+x0.z, acc[i][3]+bb[3]+x0.w };
        float4 v1 = { acc[i][4]+bb[4]+x1.x, acc[i][5]+bb[5]+x1.y,
                      acc[i][6]+bb[6]+x1.z, acc[i][7]+bb[7]+x1.w };
        *(float4*)(ob + base + bn + tx*4)      = v0;
        *(float4*)(ob + base + bn + 64 + tx*4) = v1;
    }
}

// ---------------------------------------------------------------------------
extern "C" void kernel_launch(void* const* d_in, const int* in_sizes, int n_in,
                              void* d_out, int out_size) {
    const float* x   = (const float*)d_in[0];
    const float* gnw = (const float*)d_in[1];
    const float* gnb = (const float*)d_in[2];
    const float* wq  = (const float*)d_in[3];
    const float* bq  = (const float*)d_in[4];
    const float* wk  = (const float*)d_in[5];
    const float* bk  = (const float*)d_in[6];
    const float* wv  = (const float*)d_in[7];
    const float* bv  = (const float*)d_in[8];
    const float* wo  = (const float*)d_in[9];
    const float* bo  = (const float*)d_in[10];
    float* out = (float*)d_out;

    gn_stats<<<BATCH * NGRP, 256>>>(x);
    gn_apply<<<(BATCH * CHW) / (256 * 4), 256>>>(x, gnw, gnb);

    dim3 gq(CCH / BN, (BATCH * HWN) / BM, 3);        // (4, 128, 3)
    k_qkv<<<gq, 256>>>(wq, wk, wv, bq, bk, bv);

    dim3 ga(HWN / BN, HWN / BM, BATCH);              // (32, 32, 4)
    k_qtk<<<ga, 256>>>();

    k_softmax<<<BATCH * HWN, 256>>>();

    dim3 gv(HWN / BN, CCH / BM, BATCH);              // (32, 4, 4)
    k_vpt<<<gv, 256>>>();

    dim3 gf(CCH / BN, HWN / BM, BATCH);              // (4, 32, 4)
    k_final<<<gf, 256>>>(wo, bo, x, out);
}

// round 12
// speedup vs baseline: 1.8037x; 1.8037x over previous
#include <cuda_runtime.h>
#include <cuda_bf16.h>
#include <math.h>
#include <stdint.h>

// Problem constants
#define BATCH 4
#define CCH   512
#define HWN   4096
#define NGRP  32
#define CPG   16
#define CHW   (CCH*HWN)          // 2097152 per-batch elements
#define WSZ   (CCH*CCH)          // 262144 weight elements

// ---------------------------------------------------------------------------
// Scratch buffers
// ---------------------------------------------------------------------------
__device__ __align__(256) __nv_bfloat16 g_hh[BATCH*CHW], g_hl[BATCH*CHW];
__device__ __align__(256) float g_q[BATCH*CHW], g_k[BATCH*CHW], g_v[BATCH*CHW], g_o[BATCH*CHW];
__device__ __align__(256) __nv_bfloat16 g_qth[BATCH*CHW], g_qtl[BATCH*CHW];
__device__ __align__(256) __nv_bfloat16 g_kth[BATCH*CHW], g_ktl[BATCH*CHW];
__device__ __align__(256) __nv_bfloat16 g_vh [BATCH*CHW], g_vl [BATCH*CHW];
__device__ __align__(256) __nv_bfloat16 g_oth[BATCH*CHW], g_otl[BATCH*CHW];
__device__ __align__(256) float g_attn[(size_t)BATCH*HWN*HWN];          // 268 MB
__device__ __align__(256) __nv_bfloat16 g_ph[(size_t)BATCH*HWN*HWN];
__device__ __align__(256) __nv_bfloat16 g_pl[(size_t)BATCH*HWN*HWN];
__device__ __align__(256) __nv_bfloat16 g_wh[4*WSZ], g_wl[4*WSZ];
__device__ float g_mu[BATCH*NGRP], g_rs[BATCH*NGRP];

__device__ __forceinline__ void split_bf16(float v, __nv_bfloat16& h, __nv_bfloat16& l) {
    h = __float2bfloat16(v);
    l = __float2bfloat16(v - __bfloat162float(h));
}

__device__ __forceinline__ void mma16816(float* d, const uint32_t* a, const uint32_t* b) {
    asm volatile("mma.sync.aligned.m16n8k16.row.col.f32.bf16.bf16.f32 "
                 "{%0,%1,%2,%3},{%4,%5,%6,%7},{%8,%9},{%0,%1,%2,%3};"
                 : "+f"(d[0]), "+f"(d[1]), "+f"(d[2]), "+f"(d[3])
                 : "r"(a[0]), "r"(a[1]), "r"(a[2]), "r"(a[3]), "r"(b[0]), "r"(b[1]));
}

// ---------------------------------------------------------------------------
// GroupNorm
// ---------------------------------------------------------------------------
__global__ void gn_stats(const float* __restrict__ x) {
    int bg = blockIdx.x;
    const float* p = x + (size_t)bg * (CPG * HWN);
    float s = 0.f, ss = 0.f;
    for (int i = threadIdx.x * 4; i < CPG * HWN; i += blockDim.x * 4) {
        float4 v = *(const float4*)(p + i);
        s  += v.x + v.y + v.z + v.w;
        ss += v.x*v.x + v.y*v.y + v.z*v.z + v.w*v.w;
    }
    __shared__ float sh[64];
    #pragma unroll
    for (int o = 16; o; o >>= 1) {
        s  += __shfl_down_sync(0xffffffffu, s, o);
        ss += __shfl_down_sync(0xffffffffu, ss, o);
    }
    int w = threadIdx.x >> 5, l = threadIdx.x & 31;
    if (l == 0) { sh[w] = s; sh[32 + w] = ss; }
    __syncthreads();
    if (w == 0) {
        s  = (l < (int)(blockDim.x >> 5)) ? sh[l] : 0.f;
        ss = (l < (int)(blockDim.x >> 5)) ? sh[32 + l] : 0.f;
        #pragma unroll
        for (int o = 16; o; o >>= 1) {
            s  += __shfl_down_sync(0xffffffffu, s, o);
            ss += __shfl_down_sync(0xffffffffu, ss, o);
        }
        if (l == 0) {
            float mu = s * (1.f / 65536.f);
            float var = ss * (1.f / 65536.f) - mu * mu;
            g_mu[bg] = mu;
            g_rs[bg] = rsqrtf(var + 1e-5f);
        }
    }
}

__global__ void gn_apply(const float* __restrict__ x,
                         const float* __restrict__ gw,
                         const float* __restrict__ gb) {
    size_t i = ((size_t)blockIdx.x * blockDim.x + threadIdx.x) * 4;
    if (i >= (size_t)BATCH * CHW) return;
    float4 v = *(const float4*)(x + i);
    int c  = (int)((i >> 12) & 511);
    int bg = (int)(i >> 16);
    float rs = g_rs[bg];
    float sc = rs * gw[c];
    float sb = gb[c] - g_mu[bg] * sc;
    float f0 = v.x*sc+sb, f1 = v.y*sc+sb, f2 = v.z*sc+sb, f3 = v.w*sc+sb;
    __nv_bfloat16 h0,h1,h2,h3,l0,l1,l2,l3;
    split_bf16(f0,h0,l0); split_bf16(f1,h1,l1); split_bf16(f2,h2,l2); split_bf16(f3,h3,l3);
    *(__nv_bfloat162*)(g_hh + i)     = __nv_bfloat162(h0,h1);
    *(__nv_bfloat162*)(g_hh + i + 2) = __nv_bfloat162(h2,h3);
    *(__nv_bfloat162*)(g_hl + i)     = __nv_bfloat162(l0,l1);
    *(__nv_bfloat162*)(g_hl + i + 2) = __nv_bfloat162(l2,l3);
}

// ---------------------------------------------------------------------------
// Elementwise fp32 -> bf16 hi/lo
// ---------------------------------------------------------------------------
__global__ void k_conv(const float* __restrict__ s, __nv_bfloat16* __restrict__ hi,
                       __nv_bfloat16* __restrict__ lo, int n) {
    size_t i = ((size_t)blockIdx.x * blockDim.x + threadIdx.x) * 4;
    if (i >= (size_t)n) return;
    float4 v = *(const float4*)(s + i);
    __nv_bfloat16 h0,h1,h2,h3,l0,l1,l2,l3;
    split_bf16(v.x,h0,l0); split_bf16(v.y,h1,l1); split_bf16(v.z,h2,l2); split_bf16(v.w,h3,l3);
    *(__nv_bfloat162*)(hi + i)     = __nv_bfloat162(h0,h1);
    *(__nv_bfloat162*)(hi + i + 2) = __nv_bfloat162(h2,h3);
    *(__nv_bfloat162*)(lo + i)     = __nv_bfloat162(l0,l1);
    *(__nv_bfloat162*)(lo + i + 2) = __nv_bfloat162(l2,l3);
}

// ---------------------------------------------------------------------------
// Transpose + convert: src [R x Cc] fp32 per batch -> dst [Cc x R] bf16 hi/lo
// ---------------------------------------------------------------------------
__global__ void k_tconv(const float* __restrict__ src, __nv_bfloat16* __restrict__ hi,
                        __nv_bfloat16* __restrict__ lo, int R, int Cc) {
    __shared__ float t[32][33];
    int z = blockIdx.z;
    const float* s = src + (size_t)z * CHW;
    __nv_bfloat16* ph = hi + (size_t)z * CHW;
    __nv_bfloat16* pl = lo + (size_t)z * CHW;
    int bx = blockIdx.x * 32;   // over Cc
    int by = blockIdx.y * 32;   // over R
    for (int r = threadIdx.y; r < 32; r += 8)
        t[r][threadIdx.x] = s[(size_t)(by + r) * Cc + bx + threadIdx.x];
    __syncthreads();
    for (int r = threadIdx.y; r < 32; r += 8) {
        float v = t[threadIdx.x][r];
        size_t o = (size_t)(bx + r) * R + by + threadIdx.x;
        __nv_bfloat16 h, l;
        split_bf16(v, h, l);
        ph[o] = h; pl[o] = l;
    }
}

// ---------------------------------------------------------------------------
// mma.sync bf16x3 GEMM: C[m,n] (+bias[n]) (+res[m,n]) = sum_k A[m,k]*B[n,k]
// A,B hi/lo, K-major. CTA tile 128x128, BK=32, 512 threads / 16 warps
// (32x32 warp tiles). Register-staged synchronous double buffer.
// SMEM: unswizzled, 80-byte row stride. Documented m16n8k16 fragment layout.
// ---------------------------------------------------------------------------
#define ROW_B   80              // bytes per 32-element bf16 row (64 + 16 pad)
#define TILE_B  (128*ROW_B)     // 10240
#define STAGE_B (4*TILE_B)      // 40960 : Ah, Al, Bh, Bl
#define SMEM_TOT (2*STAGE_B)    // 81920

__global__ __launch_bounds__(512, 1) void k_mma(
    const __nv_bfloat16* __restrict__ Ahi, const __nv_bfloat16* __restrict__ Alo,
    const __nv_bfloat16* __restrict__ Bhi, const __nv_bfloat16* __restrict__ Blo,
    float* __restrict__ C, const float* __restrict__ bias, const float* __restrict__ res,
    int K, int ldc, size_t sA, size_t sB, size_t sC)
{
    extern __shared__ char smem[];
    int t = threadIdx.x, wid = t >> 5, lane = t & 31;
    int z = blockIdx.z;
    size_t bm = (size_t)blockIdx.y * 128, bn = (size_t)blockIdx.x * 128;

    const __nv_bfloat16* a0 = Ahi + z * sA + bm * K;
    const __nv_bfloat16* a1 = Alo + z * sA + bm * K;
    const __nv_bfloat16* b0 = Bhi + z * sB + bn * K;
    const __nv_bfloat16* b1 = Blo + z * sB + bn * K;
    const int NC = K >> 5;

    // warp tiling: 4 (m) x 4 (n) warps, 32x32 tile each
    int mB = (wid >> 2) * 32, nB = (wid & 3) * 32;
    int g = lane >> 2, tig = lane & 3;

    // copy coords: 512 threads, one 16B chunk per tile per thread
    int crow = t >> 2, cc = t & 3;                 // row 0..127, 16B col 0..3
    size_t gcol = (size_t)crow * K + cc * 8;       // element offset
    int soff = crow * ROW_B + cc * 16;             // smem byte offset within tile

    float acc[2][4][4];
    #pragma unroll
    for (int i = 0; i < 2; i++)
        #pragma unroll
        for (int j = 0; j < 4; j++)
            #pragma unroll
            for (int q = 0; q < 4; q++) acc[i][j][q] = 0.f;

    // preload chunk 0 into stage 0 (synchronous)
    {
        char* dst = smem + soff;
        *(uint4*)(dst + 0*TILE_B) = *(const uint4*)(a0 + gcol);
        *(uint4*)(dst + 1*TILE_B) = *(const uint4*)(a1 + gcol);
        *(uint4*)(dst + 2*TILE_B) = *(const uint4*)(b0 + gcol);
        *(uint4*)(dst + 3*TILE_B) = *(const uint4*)(b1 + gcol);
    }
    __syncthreads();

    for (int ch = 0; ch < NC; ch++) {
        int s = ch & 1;
        bool hasNext = (ch + 1 < NC);
        uint4 p0, p1, p2, p3;
        if (hasNext) {
            size_t ge = gcol + (size_t)(ch + 1) * 32;
            p0 = *(const uint4*)(a0 + ge);
            p1 = *(const uint4*)(a1 + ge);
            p2 = *(const uint4*)(b0 + ge);
            p3 = *(const uint4*)(b1 + ge);
        }

        const char* stg = smem + s * STAGE_B;
        #pragma unroll
        for (int kk = 0; kk < 2; kk++) {
            // A fragments: reg q -> row = base + g + (q&1)*8, k = kk*16 + (q>>1)*8 + tig*2
            uint32_t Ah[2][4], Al[2][4];
            #pragma unroll
            for (int i = 0; i < 2; i++) {
                #pragma unroll
                for (int q = 0; q < 4; q++) {
                    int row = mB + i * 16 + g + (q & 1) * 8;
                    int kc  = kk * 16 + (q >> 1) * 8 + tig * 2;
                    int off = row * ROW_B + kc * 2;
                    Ah[i][q] = *(const uint32_t*)(stg + 0*TILE_B + off);
                    Al[i][q] = *(const uint32_t*)(stg + 1*TILE_B + off);
                }
            }
            // B fragments: reg q -> n = base + g, k = kk*16 + q*8 + tig*2
            uint32_t Bh[4][2], Bl[4][2];
            #pragma unroll
            for (int j = 0; j < 4; j++) {
                #pragma unroll
                for (int q = 0; q < 2; q++) {
                    int row = nB + j * 8 + g;
                    int kc  = kk * 16 + q * 8 + tig * 2;
                    int off = row * ROW_B + kc * 2;
                    Bh[j][q] = *(const uint32_t*)(stg + 2*TILE_B + off);
                    Bl[j][q] = *(const uint32_t*)(stg + 3*TILE_B + off);
                }
            }
            #pragma unroll
            for (int i = 0; i < 2; i++)
                #pragma unroll
                for (int j = 0; j < 4; j++) {
                    mma16816(acc[i][j], Ah[i], Bh[j]);   // hi*hi
                    mma16816(acc[i][j], Ah[i], Bl[j]);   // hi*lo
                    mma16816(acc[i][j], Al[i], Bh[j]);   // lo*hi
                }
        }

        if (hasNext) {
            char* dst = smem + (1 - s) * STAGE_B + soff;
            *(uint4*)(dst + 0*TILE_B) = p0;
            *(uint4*)(dst + 1*TILE_B) = p1;
            *(uint4*)(dst + 2*TILE_B) = p2;
            *(uint4*)(dst + 3*TILE_B) = p3;
        }
        __syncthreads();
    }

    // Epilogue: c0,c1 -> (row g, cols tig*2,+1); c2,c3 -> (row g+8)
    float* Cz = C + z * sC;
    const float* rz = res ? res + z * sC : (const float*)0;
    int cq = tig * 2;
    #pragma unroll
    for (int i = 0; i < 2; i++) {
        #pragma unroll
        for (int j = 0; j < 4; j++) {
            int n = (int)bn + nB + j * 8 + cq;
            float b0v = 0.f, b1v = 0.f;
            if (bias) { b0v = bias[n]; b1v = bias[n + 1]; }
            #pragma unroll
            for (int h = 0; h < 2; h++) {
                int m = (int)bm + mB + i * 16 + g + h * 8;
                size_t o = (size_t)m * ldc + n;
                float v0 = acc[i][j][h * 2 + 0] + b0v;
                float v1 = acc[i][j][h * 2 + 1] + b1v;
                if (rz) {
                    float2 rr = *(const float2*)(rz + o);
                    v0 += rr.x; v1 += rr.y;
                }
                float2 w = { v0, v1 };
                *(float2*)(Cz + o) = w;
            }
        }
    }
}

// ---------------------------------------------------------------------------
// Softmax over last dim (4096); writes bf16 hi/lo probabilities.
// ---------------------------------------------------------------------------
__global__ __launch_bounds__(256) void k_softmax() {
    __shared__ float buf[HWN];
    __shared__ float red[33];
    size_t row = blockIdx.x;
    const float* p = g_attn + row * HWN;
    __nv_bfloat16* ph = g_ph + row * HWN;
    __nv_bfloat16* pl = g_pl + row * HWN;
    int tid = threadIdx.x;
    float mx = -1e30f;
    for (int i = tid * 4; i < HWN; i += 1024) {
        float4 v = *(const float4*)(p + i);
        *(float4*)(buf + i) = v;
        mx = fmaxf(mx, fmaxf(fmaxf(v.x, v.y), fmaxf(v.z, v.w)));
    }
    #pragma unroll
    for (int o = 16; o; o >>= 1) mx = fmaxf(mx, __shfl_xor_sync(0xffffffffu, mx, o));
    if ((tid & 31) == 0) red[tid >> 5] = mx;
    __syncthreads();
    if (tid < 32) {
        float m2 = (tid < 8) ? red[tid] : -1e30f;
        #pragma unroll
        for (int o = 4; o; o >>= 1) m2 = fmaxf(m2, __shfl_xor_sync(0xffffffffu, m2, o));
        if (tid == 0) red[32] = m2;
    }
    __syncthreads();
    mx = red[32];
    float s = 0.f;
    for (int i = tid * 4; i < HWN; i += 1024) {
        float4 v = *(float4*)(buf + i);
        v.x = __expf(v.x - mx); v.y = __expf(v.y - mx);
        v.z = __expf(v.z - mx); v.w = __expf(v.w - mx);
        *(float4*)(buf + i) = v;
        s += v.x + v.y + v.z + v.w;
    }
    #pragma unroll
    for (int o = 16; o; o >>= 1) s += __shfl_xor_sync(0xffffffffu, s, o);
    if ((tid & 31) == 0) red[tid >> 5] = s;
    __syncthreads();
    if (tid < 32) {
        float s2 = (tid < 8) ? red[tid] : 0.f;
        #pragma unroll
        for (int o = 4; o; o >>= 1) s2 += __shfl_xor_sync(0xffffffffu, s2, o);
        if (tid == 0) red[32] = s2;
    }
    __syncthreads();
    float inv = 1.f / red[32];
    for (int i = tid * 4; i < HWN; i += 1024) {
        float4 v = *(float4*)(buf + i);
        float f0 = v.x*inv, f1 = v.y*inv, f2 = v.z*inv, f3 = v.w*inv;
        __nv_bfloat16 h0,h1,h2,h3,l0,l1,l2,l3;
        split_bf16(f0,h0,l0); split_bf16(f1,h1,l1); split_bf16(f2,h2,l2); split_bf16(f3,h3,l3);
        *(__nv_bfloat162*)(ph + i)     = __nv_bfloat162(h0,h1);
        *(__nv_bfloat162*)(ph + i + 2) = __nv_bfloat162(h2,h3);
        *(__nv_bfloat162*)(pl + i)     = __nv_bfloat162(l0,l1);
        *(__nv_bfloat162*)(pl + i + 2) = __nv_bfloat162(l2,l3);
    }
}

// ---------------------------------------------------------------------------
extern "C" void kernel_launch(void* const* d_in, const int* in_sizes, int n_in,
                              void* d_out, int out_size) {
    const float* x   = (const float*)d_in[0];
    const float* gnw = (const float*)d_in[1];
    const float* gnb = (const float*)d_in[2];
    const float* wq  = (const float*)d_in[3];
    const float* bq  = (const float*)d_in[4];
    const float* wk  = (const float*)d_in[5];
    const float* bk  = (const float*)d_in[6];
    const float* wv  = (const float*)d_in[7];
    const float* bv  = (const float*)d_in[8];
    const float* wo  = (const float*)d_in[9];
    const float* bo  = (const float*)d_in[10];
    float* out = (float*)d_out;

    void *p_hh, *p_hl, *p_q, *p_k, *p_v, *p_o, *p_qth, *p_qtl, *p_kth, *p_ktl,
         *p_vh, *p_vl, *p_oth, *p_otl, *p_attn, *p_ph, *p_pl, *p_wh, *p_wl;
    cudaGetSymbolAddress(&p_hh, g_hh);   cudaGetSymbolAddress(&p_hl, g_hl);
    cudaGetSymbolAddress(&p_q, g_q);     cudaGetSymbolAddress(&p_k, g_k);
    cudaGetSymbolAddress(&p_v, g_v);     cudaGetSymbolAddress(&p_o, g_o);
    cudaGetSymbolAddress(&p_qth, g_qth); cudaGetSymbolAddress(&p_qtl, g_qtl);
    cudaGetSymbolAddress(&p_kth, g_kth); cudaGetSymbolAddress(&p_ktl, g_ktl);
    cudaGetSymbolAddress(&p_vh, g_vh);   cudaGetSymbolAddress(&p_vl, g_vl);
    cudaGetSymbolAddress(&p_oth, g_oth); cudaGetSymbolAddress(&p_otl, g_otl);
    cudaGetSymbolAddress(&p_attn, g_attn);
    cudaGetSymbolAddress(&p_ph, g_ph);   cudaGetSymbolAddress(&p_pl, g_pl);
    cudaGetSymbolAddress(&p_wh, g_wh);   cudaGetSymbolAddress(&p_wl, g_wl);

    __nv_bfloat16* hh = (__nv_bfloat16*)p_hh; __nv_bfloat16* hl = (__nv_bfloat16*)p_hl;
    float* qf = (float*)p_q; float* kf = (float*)p_k; float* vf = (float*)p_v; float* of = (float*)p_o;
    __nv_bfloat16* wh = (__nv_bfloat16*)p_wh; __nv_bfloat16* wl = (__nv_bfloat16*)p_wl;

    cudaFuncSetAttribute(k_mma, cudaFuncAttributeMaxDynamicSharedMemorySize, SMEM_TOT);

    // GroupNorm -> h hi/lo
    gn_stats<<<BATCH * NGRP, 256>>>(x);
    gn_apply<<<(BATCH * CHW) / 1024, 256>>>(x, gnw, gnb);

    // weights -> hi/lo
    k_conv<<<WSZ / 1024, 256>>>(wq, wh + 0*WSZ, wl + 0*WSZ, WSZ);
    k_conv<<<WSZ / 1024, 256>>>(wk, wh + 1*WSZ, wl + 1*WSZ, WSZ);
    k_conv<<<WSZ / 1024, 256>>>(wv, wh + 2*WSZ, wl + 2*WSZ, WSZ);
    k_conv<<<WSZ / 1024, 256>>>(wo, wh + 3*WSZ, wl + 3*WSZ, WSZ);

    // QKV projections: M=16384, N=512, K=512
    dim3 gq(4, 128, 1);
    k_mma<<<gq, 512, SMEM_TOT>>>(hh, hl, wh + 0*WSZ, wl + 0*WSZ, qf, bq, 0, 512, 512, 0, 0, 0);
    k_mma<<<gq, 512, SMEM_TOT>>>(hh, hl, wh + 1*WSZ, wl + 1*WSZ, kf, bk, 0, 512, 512, 0, 0, 0);
    k_mma<<<gq, 512, SMEM_TOT>>>(hh, hl, wh + 2*WSZ, wl + 2*WSZ, vf, bv, 0, 512, 512, 0, 0, 0);

    // transpose Q,K to n-major (4096x512 per batch); V stays k-major over m
    dim3 gt(HWN / 32, CCH / 32, BATCH);
    k_tconv<<<gt, dim3(32, 8)>>>(qf, (__nv_bfloat16*)p_qth, (__nv_bfloat16*)p_qtl, CCH, HWN);
    k_tconv<<<gt, dim3(32, 8)>>>(kf, (__nv_bfloat16*)p_kth, (__nv_bfloat16*)p_ktl, CCH, HWN);
    k_conv<<<(BATCH * CHW) / 1024, 256>>>(vf, (__nv_bfloat16*)p_vh, (__nv_bfloat16*)p_vl, BATCH * CHW);

    // attn logits: per batch M=N=4096, K=512, C row stride (ldc) = HWN
    // (R4-R9 bug was here: K/ldc were swapped)
    dim3 ga(32, 32, BATCH);
    k_mma<<<ga, 512, SMEM_TOT>>>((__nv_bfloat16*)p_qth, (__nv_bfloat16*)p_qtl,
                                 (__nv_bfloat16*)p_kth, (__nv_bfloat16*)p_ktl,
                                 (float*)p_attn, 0, 0, 512, HWN,
                                 (size_t)CHW, (size_t)CHW, (size_t)HWN * HWN);

    // softmax -> P hi/lo
    k_softmax<<<BATCH * HWN, 256>>>();

    // O = V @ P^T: per batch M=512, N=4096, K=4096
    dim3 gv(32, 4, BATCH);
    k_mma<<<gv, 512, SMEM_TOT>>>((__nv_bfloat16*)p_vh, (__nv_bfloat16*)p_vl,
                                 (__nv_bfloat16*)p_ph, (__nv_bfloat16*)p_pl,
                                 of, 0, 0, HWN, HWN,
                                 (size_t)CHW, (size_t)HWN * HWN, (size_t)CHW);

    // transpose O -> n-major
    k_tconv<<<gt, dim3(32, 8)>>>(of, (__nv_bfloat16*)p_oth, (__nv_bfloat16*)p_otl, CCH, HWN);

    // final projection + bias + residual: per batch M=4096, N=512, K=512
    dim3 gf(4, 32, BATCH);
    k_mma<<<gf, 512, SMEM_TOT>>>((__nv_bfloat16*)p_oth, (__nv_bfloat16*)p_otl,
                                 wh + 3*WSZ, wl + 3*WSZ,
                                 out, bo, x, 512, 512,
                                 (size_t)CHW, 0, (size_t)CHW);
}

// round 17
// speedup vs baseline: 1.8199x; 1.0090x over previous
#include <cuda_runtime.h>
#include <cuda_bf16.h>
#include <math.h>
#include <stdint.h>

// Problem constants
#define BATCH 4
#define CCH   512
#define HWN   4096
#define NGRP  32
#define CPG   16
#define CHW   (CCH*HWN)          // 2097152 per-batch elements
#define WSZ   (CCH*CCH)          // 262144 weight elements

// ---------------------------------------------------------------------------
// Scratch buffers
// ---------------------------------------------------------------------------
__device__ __align__(256) __nv_bfloat16 g_hh[BATCH*CHW], g_hl[BATCH*CHW];
__device__ __align__(256) float g_q[BATCH*CHW], g_k[BATCH*CHW], g_v[BATCH*CHW], g_o[BATCH*CHW];
__device__ __align__(256) __nv_bfloat16 g_qth[BATCH*CHW], g_qtl[BATCH*CHW];
__device__ __align__(256) __nv_bfloat16 g_kth[BATCH*CHW], g_ktl[BATCH*CHW];
__device__ __align__(256) __nv_bfloat16 g_vh [BATCH*CHW], g_vl [BATCH*CHW];
__device__ __align__(256) __nv_bfloat16 g_oth[BATCH*CHW], g_otl[BATCH*CHW];
__device__ __align__(256) float g_attn[(size_t)BATCH*HWN*HWN];          // 268 MB
__device__ __align__(256) __nv_bfloat16 g_ph[(size_t)BATCH*HWN*HWN];
__device__ __align__(256) __nv_bfloat16 g_pl[(size_t)BATCH*HWN*HWN];
__device__ __align__(256) __nv_bfloat16 g_wh[4*WSZ], g_wl[4*WSZ];
__device__ float g_mu[BATCH*NGRP], g_rs[BATCH*NGRP];

__device__ __forceinline__ void split_bf16(float v, __nv_bfloat16& h, __nv_bfloat16& l) {
    h = __float2bfloat16(v);
    l = __float2bfloat16(v - __bfloat162float(h));
}

__device__ __forceinline__ uint32_t smem_u32(const void* p) {
    uint32_t a;
    asm("{ .reg .u64 t; cvta.to.shared.u64 t, %1; cvt.u32.u64 %0, t; }" : "=r"(a) : "l"(p));
    return a;
}
__device__ __forceinline__ void cpa16(uint32_t so, const void* gp) {
    asm volatile("cp.async.cg.shared.global [%0], [%1], 16;"
                 :: "r"(so), "l"(__cvta_generic_to_global(gp)) : "memory");
}
#define CPA_COMMIT() asm volatile("cp.async.commit_group;" ::: "memory")
#define CPA_WAIT(N)  asm volatile("cp.async.wait_group %0;" :: "n"(N) : "memory")

__device__ __forceinline__ void ldm4(uint32_t* r, uint32_t addr) {
    asm volatile("ldmatrix.sync.aligned.m8n8.x4.shared.b16 {%0,%1,%2,%3}, [%4];"
                 : "=r"(r[0]), "=r"(r[1]), "=r"(r[2]), "=r"(r[3]) : "r"(addr));
}
__device__ __forceinline__ void mma16816(float* d, const uint32_t* a, const uint32_t* b) {
    asm volatile("mma.sync.aligned.m16n8k16.row.col.f32.bf16.bf16.f32 "
                 "{%0,%1,%2,%3},{%4,%5,%6,%7},{%8,%9},{%0,%1,%2,%3};"
                 : "+f"(d[0]), "+f"(d[1]), "+f"(d[2]), "+f"(d[3])
                 : "r"(a[0]), "r"(a[1]), "r"(a[2]), "r"(a[3]), "r"(b[0]), "r"(b[1]));
}

// ---------------------------------------------------------------------------
// GroupNorm
// ---------------------------------------------------------------------------
__global__ void gn_stats(const float* __restrict__ x) {
    int bg = blockIdx.x;
    const float* p = x + (size_t)bg * (CPG * HWN);
    float s = 0.f, ss = 0.f;
    for (int i = threadIdx.x * 4; i < CPG * HWN; i += blockDim.x * 4) {
        float4 v = *(const float4*)(p + i);
        s  += v.x + v.y + v.z + v.w;
        ss += v.x*v.x + v.y*v.y + v.z*v.z + v.w*v.w;
    }
    __shared__ float sh[64];
    #pragma unroll
    for (int o = 16; o; o >>= 1) {
        s  += __shfl_down_sync(0xffffffffu, s, o);
        ss += __shfl_down_sync(0xffffffffu, ss, o);
    }
    int w = threadIdx.x >> 5, l = threadIdx.x & 31;
    if (l == 0) { sh[w] = s; sh[32 + w] = ss; }
    __syncthreads();
    if (w == 0) {
        s  = (l < (int)(blockDim.x >> 5)) ? sh[l] : 0.f;
        ss = (l < (int)(blockDim.x >> 5)) ? sh[32 + l] : 0.f;
        #pragma unroll
        for (int o = 16; o; o >>= 1) {
            s  += __shfl_down_sync(0xffffffffu, s, o);
            ss += __shfl_down_sync(0xffffffffu, ss, o);
        }
        if (l == 0) {
            float mu = s * (1.f / 65536.f);
            float var = ss * (1.f / 65536.f) - mu * mu;
            g_mu[bg] = mu;
            g_rs[bg] = rsqrtf(var + 1e-5f);
        }
    }
}

__global__ void gn_apply(const float* __restrict__ x,
                         const float* __restrict__ gw,
                         const float* __restrict__ gb) {
    size_t i = ((size_t)blockIdx.x * blockDim.x + threadIdx.x) * 4;
    if (i >= (size_t)BATCH * CHW) return;
    float4 v = *(const float4*)(x + i);
    int c  = (int)((i >> 12) & 511);
    int bg = (int)(i >> 16);
    float rs = g_rs[bg];
    float sc = rs * gw[c];
    float sb = gb[c] - g_mu[bg] * sc;
    float f0 = v.x*sc+sb, f1 = v.y*sc+sb, f2 = v.z*sc+sb, f3 = v.w*sc+sb;
    __nv_bfloat16 h0,h1,h2,h3,l0,l1,l2,l3;
    split_bf16(f0,h0,l0); split_bf16(f1,h1,l1); split_bf16(f2,h2,l2); split_bf16(f3,h3,l3);
    *(__nv_bfloat162*)(g_hh + i)     = __nv_bfloat162(h0,h1);
    *(__nv_bfloat162*)(g_hh + i + 2) = __nv_bfloat162(h2,h3);
    *(__nv_bfloat162*)(g_hl + i)     = __nv_bfloat162(l0,l1);
    *(__nv_bfloat162*)(g_hl + i + 2) = __nv_bfloat162(l2,l3);
}

// ---------------------------------------------------------------------------
// Elementwise fp32 -> bf16 hi/lo
// ---------------------------------------------------------------------------
__global__ void k_conv(const float* __restrict__ s, __nv_bfloat16* __restrict__ hi,
                       __nv_bfloat16* __restrict__ lo, int n) {
    size_t i = ((size_t)blockIdx.x * blockDim.x + threadIdx.x) * 4;
    if (i >= (size_t)n) return;
    float4 v = *(const float4*)(s + i);
    __nv_bfloat16 h0,h1,h2,h3,l0,l1,l2,l3;
    split_bf16(v.x,h0,l0); split_bf16(v.y,h1,l1); split_bf16(v.z,h2,l2); split_bf16(v.w,h3,l3);
    *(__nv_bfloat162*)(hi + i)     = __nv_bfloat162(h0,h1);
    *(__nv_bfloat162*)(hi + i + 2) = __nv_bfloat162(h2,h3);
    *(__nv_bfloat162*)(lo + i)     = __nv_bfloat162(l0,l1);
    *(__nv_bfloat162*)(lo + i + 2) = __nv_bfloat162(l2,l3);
}

// ---------------------------------------------------------------------------
// Transpose + convert: src [R x Cc] fp32 per batch -> dst [Cc x R] bf16 hi/lo
// ---------------------------------------------------------------------------
__global__ void k_tconv(const float* __restrict__ src, __nv_bfloat16* __restrict__ hi,
                        __nv_bfloat16* __restrict__ lo, int R, int Cc) {
    __shared__ float t[32][33];
    int z = blockIdx.z;
    const float* s = src + (size_t)z * CHW;
    __nv_bfloat16* ph = hi + (size_t)z * CHW;
    __nv_bfloat16* pl = lo + (size_t)z * CHW;
    int bx = blockIdx.x * 32;   // over Cc
    int by = blockIdx.y * 32;   // over R
    for (int r = threadIdx.y; r < 32; r += 8)
        t[r][threadIdx.x] = s[(size_t)(by + r) * Cc + bx + threadIdx.x];
    __syncthreads();
    for (int r = threadIdx.y; r < 32; r += 8) {
        float v = t[threadIdx.x][r];
        size_t o = (size_t)(bx + r) * R + by + threadIdx.x;
        __nv_bfloat16 h, l;
        split_bf16(v, h, l);
        ph[o] = h; pl[o] = l;
    }
}

// ---------------------------------------------------------------------------
// mma.sync bf16x3 GEMM: C[m,n] (+bias[n]) (+res[m,n]) = sum_k A[m,k]*B[n,k]
// A,B hi/lo, K-major. CTA tile 128x128, BK=32, 512 threads / 16 warps
// (32x32 warp tiles). cp.async double buffer + ldmatrix fragment loads.
// SMEM: unswizzled, 80-byte row stride (conflict-free for cp.async stores
// and for ldmatrix x4 phases: 8 rows at stride 80B hit 8 distinct 16B bank
// groups). Fragment maps follow the documented m16n8k16 layout exactly.
// ---------------------------------------------------------------------------
#define ROW_B   80              // bytes per 32-element bf16 row (64 + 16 pad)
#define TILE_B  (128*ROW_B)     // 10240
#define STAGE_B (4*TILE_B)      // 40960 : Ah, Al, Bh, Bl
#define SMEM_TOT (2*STAGE_B)    // 81920

__global__ __launch_bounds__(512, 1) void k_mma(
    const __nv_bfloat16* __restrict__ Ahi, const __nv_bfloat16* __restrict__ Alo,
    const __nv_bfloat16* __restrict__ Bhi, const __nv_bfloat16* __restrict__ Blo,
    float* __restrict__ C, const float* __restrict__ bias, const float* __restrict__ res,
    int K, int ldc, size_t sA, size_t sB, size_t sC)
{
    extern __shared__ char smem[];
    uint32_t sbase = smem_u32(smem);
    int t = threadIdx.x, wid = t >> 5, lane = t & 31;
    int z = blockIdx.z;
    size_t bm = (size_t)blockIdx.y * 128, bn = (size_t)blockIdx.x * 128;

    const __nv_bfloat16* a0 = Ahi + z * sA + bm * K;
    const __nv_bfloat16* a1 = Alo + z * sA + bm * K;
    const __nv_bfloat16* b0 = Bhi + z * sB + bn * K;
    const __nv_bfloat16* b1 = Blo + z * sB + bn * K;
    const int NC = K >> 5;

    // warp tiling: 4 (m) x 4 (n) warps, 32x32 tile each
    int mB = (wid >> 2) * 32, nB = (wid & 3) * 32;
    int g = lane >> 2, tig = lane & 3;

    // copy coords: 512 threads, one 16B chunk per tile per thread
    int crow = t >> 2, cc = t & 3;                 // row 0..127, 16B col 0..3
    size_t gcol = (size_t)crow * K + cc * 8;       // element offset
    uint32_t soff = (uint32_t)(crow * ROW_B + cc * 16);

    // ldmatrix per-lane offsets (byte offsets within a tile)
    //   A x4: rows (base + (lane&15)), k-half by lane>=16 -> {a0,a1,a2,a3}
    int arow_l = lane & 15;
    int akoff_l = ((lane >> 4) & 1) * 16;
    //   B x4 (n16 pair): rows base + (lane&7) + ((lane>>4)&1)*8, k-half by bit3
    int brow_l = (lane & 7) + ((lane >> 4) & 1) * 8;
    int bkoff_l = ((lane >> 3) & 1) * 16;

    float acc[2][4][4];
    #pragma unroll
    for (int i = 0; i < 2; i++)
        #pragma unroll
        for (int j = 0; j < 4; j++)
            #pragma unroll
            for (int q = 0; q < 4; q++) acc[i][j][q] = 0.f;

#define ISSUE_STAGE(CH, S) {                                                    \
        size_t ge = gcol + (size_t)(CH) * 32;                                   \
        uint32_t so = sbase + (S) * STAGE_B + soff;                             \
        cpa16(so + 0*TILE_B, a0 + ge);                                          \
        cpa16(so + 1*TILE_B, a1 + ge);                                          \
        cpa16(so + 2*TILE_B, b0 + ge);                                          \
        cpa16(so + 3*TILE_B, b1 + ge);                                          \
        CPA_COMMIT();                                                           \
    }

    ISSUE_STAGE(0, 0)

    for (int ch = 0; ch < NC; ch++) {
        int s = ch & 1;
        if (ch + 1 < NC) {
            ISSUE_STAGE(ch + 1, 1 - s)
            CPA_WAIT(1);
        } else {
            CPA_WAIT(0);
        }
        __syncthreads();

        uint32_t stg = sbase + s * STAGE_B;
        #pragma unroll
        for (int kk = 0; kk < 2; kk++) {
            // A fragments: 2 m16 tiles, hi & lo
            uint32_t Ah[2][4], Al[2][4];
            #pragma unroll
            for (int i = 0; i < 2; i++) {
                uint32_t off = (uint32_t)((mB + i*16 + arow_l) * ROW_B + kk*32 + akoff_l);
                ldm4(Ah[i], stg + 0*TILE_B + off);
                ldm4(Al[i], stg + 1*TILE_B + off);
            }
            // B fragments: 2 n16 pairs (covering 4 n8 tiles), hi & lo
            uint32_t Bh[2][4], Bl[2][4];
            #pragma unroll
            for (int jp = 0; jp < 2; jp++) {
                uint32_t off = (uint32_t)((nB + jp*16 + brow_l) * ROW_B + kk*32 + bkoff_l);
                ldm4(Bh[jp], stg + 2*TILE_B + off);
                ldm4(Bl[jp], stg + 3*TILE_B + off);
            }
            #pragma unroll
            for (int i = 0; i < 2; i++)
                #pragma unroll
                for (int j = 0; j < 4; j++) {
                    const uint32_t* bh = &Bh[j >> 1][(j & 1) * 2];
                    const uint32_t* bl = &Bl[j >> 1][(j & 1) * 2];
                    mma16816(acc[i][j], Ah[i], bh);   // hi*hi
                    mma16816(acc[i][j], Ah[i], bl);   // hi*lo
                    mma16816(acc[i][j], Al[i], bh);   // lo*hi
                }
        }
        __syncthreads();
    }
#undef ISSUE_STAGE

    // Epilogue: c0,c1 -> (row g, cols tig*2,+1); c2,c3 -> (row g+8)
    float* Cz = C + z * sC;
    const float* rz = res ? res + z * sC : (const float*)0;
    int cq = tig * 2;
    #pragma unroll
    for (int i = 0; i < 2; i++) {
        #pragma unroll
        for (int j = 0; j < 4; j++) {
            int n = (int)bn + nB + j * 8 + cq;
            float b0v = 0.f, b1v = 0.f;
            if (bias) { b0v = bias[n]; b1v = bias[n + 1]; }
            #pragma unroll
            for (int h = 0; h < 2; h++) {
                int m = (int)bm + mB + i * 16 + g + h * 8;
                size_t o = (size_t)m * ldc + n;
                float v0 = acc[i][j][h * 2 + 0] + b0v;
                float v1 = acc[i][j][h * 2 + 1] + b1v;
                if (rz) {
                    float2 rr = *(const float2*)(rz + o);
                    v0 += rr.x; v1 += rr.y;
                }
                float2 w = { v0, v1 };
                *(float2*)(Cz + o) = w;
            }
        }
    }
}

// ---------------------------------------------------------------------------
// Softmax over last dim (4096); writes bf16 hi/lo probabilities.
// ---------------------------------------------------------------------------
__global__ __launch_bounds__(256) void k_softmax() {
    __shared__ float buf[HWN];
    __shared__ float red[33];
    size_t row = blockIdx.x;
    const float* p = g_attn + row * HWN;
    __nv_bfloat16* ph = g_ph + row * HWN;
    __nv_bfloat16* pl = g_pl + row * HWN;
    int tid = threadIdx.x;
    float mx = -1e30f;
    for (int i = tid * 4; i < HWN; i += 1024) {
        float4 v = *(const float4*)(p + i);
        *(float4*)(buf + i) = v;
        mx = fmaxf(mx, fmaxf(fmaxf(v.x, v.y), fmaxf(v.z, v.w)));
    }
    #pragma unroll
    for (int o = 16; o; o >>= 1) mx = fmaxf(mx, __shfl_xor_sync(0xffffffffu, mx, o));
    if ((tid & 31) == 0) red[tid >> 5] = mx;
    __syncthreads();
    if (tid < 32) {
        float m2 = (tid < 8) ? red[tid] : -1e30f;
        #pragma unroll
        for (int o = 4; o; o >>= 1) m2 = fmaxf(m2, __shfl_xor_sync(0xffffffffu, m2, o));
        if (tid == 0) red[32] = m2;
    }
    __syncthreads();
    mx = red[32];
    float s = 0.f;
    for (int i = tid * 4; i < HWN; i += 1024) {
        float4 v = *(float4*)(buf + i);
        v.x = __expf(v.x - mx); v.y = __expf(v.y - mx);
        v.z = __expf(v.z - mx); v.w = __expf(v.w - mx);
        *(float4*)(buf + i) = v;
        s += v.x + v.y + v.z + v.w;
    }
    #pragma unroll
    for (int o = 16; o; o >>= 1) s += __shfl_xor_sync(0xffffffffu, s, o);
    if ((tid & 31) == 0) red[tid >> 5] = s;
    __syncthreads();
    if (tid < 32) {
        float s2 = (tid < 8) ? red[tid] : 0.f;
        #pragma unroll
        for (int o = 4; o; o >>= 1) s2 += __shfl_xor_sync(0xffffffffu, s2, o);
        if (tid == 0) red[32] = s2;
    }
    __syncthreads();
    float inv = 1.f / red[32];
    for (int i = tid * 4; i < HWN; i += 1024) {
        float4 v = *(float4*)(buf + i);
        float f0 = v.x*inv, f1 = v.y*inv, f2 = v.z*inv, f3 = v.w*inv;
        __nv_bfloat16 h0,h1,h2,h3,l0,l1,l2,l3;
        split_bf16(f0,h0,l0); split_bf16(f1,h1,l1); split_bf16(f2,h2,l2); split_bf16(f3,h3,l3);
        *(__nv_bfloat162*)(ph + i)     = __nv_bfloat162(h0,h1);
        *(__nv_bfloat162*)(ph + i + 2) = __nv_bfloat162(h2,h3);
        *(__nv_bfloat162*)(pl + i)     = __nv_bfloat162(l0,l1);
        *(__nv_bfloat162*)(pl + i + 2) = __nv_bfloat162(l2,l3);
    }
}

// ---------------------------------------------------------------------------
extern "C" void kernel_launch(void* const* d_in, const int* in_sizes, int n_in,
                              void* d_out, int out_size) {
    const float* x   = (const float*)d_in[0];
    const float* gnw = (const float*)d_in[1];
    const float* gnb = (const float*)d_in[2];
    const float* wq  = (const float*)d_in[3];
    const float* bq  = (const float*)d_in[4];
    const float* wk  = (const float*)d_in[5];
    const float* bk  = (const float*)d_in[6];
    const float* wv  = (const float*)d_in[7];
    const float* bv  = (const float*)d_in[8];
    const float* wo  = (const float*)d_in[9];
    const float* bo  = (const float*)d_in[10];
    float* out = (float*)d_out;

    void *p_hh, *p_hl, *p_q, *p_k, *p_v, *p_o, *p_qth, *p_qtl, *p_kth, *p_ktl,
         *p_vh, *p_vl, *p_oth, *p_otl, *p_attn, *p_ph, *p_pl, *p_wh, *p_wl;
    cudaGetSymbolAddress(&p_hh, g_hh);   cudaGetSymbolAddress(&p_hl, g_hl);
    cudaGetSymbolAddress(&p_q, g_q);     cudaGetSymbolAddress(&p_k, g_k);
    cudaGetSymbolAddress(&p_v, g_v);     cudaGetSymbolAddress(&p_o, g_o);
    cudaGetSymbolAddress(&p_qth, g_qth); cudaGetSymbolAddress(&p_qtl, g_qtl);
    cudaGetSymbolAddress(&p_kth, g_kth); cudaGetSymbolAddress(&p_ktl, g_ktl);
    cudaGetSymbolAddress(&p_vh, g_vh);   cudaGetSymbolAddress(&p_vl, g_vl);
    cudaGetSymbolAddress(&p_oth, g_oth); cudaGetSymbolAddress(&p_otl, g_otl);
    cudaGetSymbolAddress(&p_attn, g_attn);
    cudaGetSymbolAddress(&p_ph, g_ph);   cudaGetSymbolAddress(&p_pl, g_pl);
    cudaGetSymbolAddress(&p_wh, g_wh);   cudaGetSymbolAddress(&p_wl, g_wl);

    __nv_bfloat16* hh = (__nv_bfloat16*)p_hh; __nv_bfloat16* hl = (__nv_bfloat16*)p_hl;
    float* qf = (float*)p_q; float* kf = (float*)p_k; float* vf = (float*)p_v; float* of = (float*)p_o;
    __nv_bfloat16* wh = (__nv_bfloat16*)p_wh; __nv_bfloat16* wl = (__nv_bfloat16*)p_wl;

    cudaFuncSetAttribute(k_mma, cudaFuncAttributeMaxDynamicSharedMemorySize, SMEM_TOT);

    // GroupNorm -> h hi/lo
    gn_stats<<<BATCH * NGRP, 256>>>(x);
    gn_apply<<<(BATCH * CHW) / 1024, 256>>>(x, gnw, gnb);

    // weights -> hi/lo
    k_conv<<<WSZ / 1024, 256>>>(wq, wh + 0*WSZ, wl + 0*WSZ, WSZ);
    k_conv<<<WSZ / 1024, 256>>>(wk, wh + 1*WSZ, wl + 1*WSZ, WSZ);
    k_conv<<<WSZ / 1024, 256>>>(wv, wh + 2*WSZ, wl + 2*WSZ, WSZ);
    k_conv<<<WSZ / 1024, 256>>>(wo, wh + 3*WSZ, wl + 3*WSZ, WSZ);

    // QKV projections: M=16384, N=512, K=512
    dim3 gq(4, 128, 1);
    k_mma<<<gq, 512, SMEM_TOT>>>(hh, hl, wh + 0*WSZ, wl + 0*WSZ, qf, bq, 0, 512, 512, 0, 0, 0);
    k_mma<<<gq, 512, SMEM_TOT>>>(hh, hl, wh + 1*WSZ, wl + 1*WSZ, kf, bk, 0, 512, 512, 0, 0, 0);
    k_mma<<<gq, 512, SMEM_TOT>>>(hh, hl, wh + 2*WSZ, wl + 2*WSZ, vf, bv, 0, 512, 512, 0, 0, 0);

    // transpose Q,K to n-major (4096x512 per batch); V stays k-major over m
    dim3 gt(HWN / 32, CCH / 32, BATCH);
    k_tconv<<<gt, dim3(32, 8)>>>(qf, (__nv_bfloat16*)p_qth, (__nv_bfloat16*)p_qtl, CCH, HWN);
    k_tconv<<<gt, dim3(32, 8)>>>(kf, (__nv_bfloat16*)p_kth, (__nv_bfloat16*)p_ktl, CCH, HWN);
    k_conv<<<(BATCH * CHW) / 1024, 256>>>(vf, (__nv_bfloat16*)p_vh, (__nv_bfloat16*)p_vl, BATCH * CHW);

    // attn logits: per batch M=N=4096, K=512, ldc=HWN
    dim3 ga(32, 32, BATCH);
    k_mma<<<ga, 512, SMEM_TOT>>>((__nv_bfloat16*)p_qth, (__nv_bfloat16*)p_qtl,
                                 (__nv_bfloat16*)p_kth, (__nv_bfloat16*)p_ktl,
                                 (float*)p_attn, 0, 0, 512, HWN,
                                 (size_t)CHW, (size_t)CHW, (size_t)HWN * HWN);

    // softmax -> P hi/lo
    k_softmax<<<BATCH * HWN, 256>>>();

    // O = V @ P^T: per batch M=512, N=4096, K=4096
    dim3 gv(32, 4, BATCH);
    k_mma<<<gv, 512, SMEM_TOT>>>((__nv_bfloat16*)p_vh, (__nv_bfloat16*)p_vl,
                                 (__nv_bfloat16*)p_ph, (__nv_bfloat16*)p_pl,
                                 of, 0, 0, HWN, HWN,
                                 (size_t)CHW, (size_t)HWN * HWN, (size_t)CHW);

    // transpose O -> n-major
    k_tconv<<<gt, dim3(32, 8)>>>(of, (__nv_bfloat16*)p_oth, (__nv_bfloat16*)p_otl, CCH, HWN);

    // final projection + bias + residual: per batch M=4096, N=512, K=512
    dim3 gf(4, 32, BATCH);
    k_mma<<<gf, 512, SMEM_TOT>>>((__nv_bfloat16*)p_oth, (__nv_bfloat16*)p_otl,
                                 wh + 3*WSZ, wl + 3*WSZ,
                                 out, bo, x, 512, 512,
                                 (size_t)CHW, 0, (size_t)CHW);
}